// round 1
// baseline (speedup 1.0000x reference)
#include <cuda_runtime.h>
#include <math.h>

// Problem constants
#define TT    4096   // tokens = B*S
#define DIN   4096
#define DOUT  4096
#define NE    8
#define NRTR  64     // E * K_RTR
#define KEXT  272    // 256 (E*K_EXP) + 8 (w->bias) + 8 zero pad -> 17 * BK(16)

// Scratch (device globals; allocation is forbidden)
__device__ float g_gl[TT * NRTR];       // gate logits [T, 64]
__device__ float g_w[TT * NE];          // dense routed weights [T, 8]
__device__ float g_aext[TT * KEXT];     // [h' (scaled) | w | 0pad] per token
__device__ float g_bext[DOUT * KEXT];   // [u_flat | bias^T | 0pad] per out-col

// ---------------------------------------------------------------------------
// Build B-extension matrix: g_bext[n, k] = u[e][n][r] (k=e*32+r, k<256),
// expert_bias[e][n] (k=256+e), 0 (pad).
// ---------------------------------------------------------------------------
__global__ void bext_kernel(const float* __restrict__ u, const float* __restrict__ eb) {
    int idx = blockIdx.x * blockDim.x + threadIdx.x;
    if (idx >= DOUT * KEXT) return;
    int n = idx / KEXT;
    int k = idx - n * KEXT;
    float v = 0.f;
    if (k < 256) {
        int e = k >> 5, r = k & 31;
        v = u[(e * DOUT + n) * 32 + r];
    } else if (k < 264) {
        v = eb[(k - 256) * DOUT + n];
    }
    g_bext[idx] = v;
}

// ---------------------------------------------------------------------------
// Routing: L2 norm over K_RTR of gate logits -> softmax -> top2 -> renorm.
// Writes dense per-expert weights to g_w and to the w-slot of g_aext.
// ---------------------------------------------------------------------------
__global__ void routing_kernel() {
    int t = blockIdx.x * blockDim.x + threadIdx.x;
    if (t >= TT) return;
    float rl[NE];
    #pragma unroll
    for (int e = 0; e < NE; e++) {
        float s = 0.f;
        #pragma unroll
        for (int r = 0; r < 8; r++) {
            float v = g_gl[t * NRTR + e * 8 + r];
            s += v * v;
        }
        rl[e] = sqrtf(s);
    }
    int i1 = 0;
    #pragma unroll
    for (int e = 1; e < NE; e++) if (rl[e] > rl[i1]) i1 = e;
    int i2 = (i1 == 0) ? 1 : 0;
    #pragma unroll
    for (int e = 0; e < NE; e++) if (e != i1 && rl[e] > rl[i2]) i2 = e;
    // top2 weights renormalized: softmax monotone -> top2 of logits;
    // w1 = exp(r1)/(exp(r1)+exp(r2)), stable form:
    float e2 = expf(rl[i2] - rl[i1]);
    float inv = 1.f / (1.f + e2);
    float w1 = inv, w2 = e2 * inv;
    #pragma unroll
    for (int e = 0; e < NE; e++) {
        float v = (e == i1) ? w1 : ((e == i2) ? w2 : 0.f);
        g_w[t * NE + e] = v;
        g_aext[t * KEXT + 256 + e] = v;
    }
    #pragma unroll
    for (int p = 0; p < 8; p++) g_aext[t * KEXT + 264 + p] = 0.f;
}

// ---------------------------------------------------------------------------
// Generic NT-SGEMM: C[M,N] = A[M,K] * B[N,K]^T, K = DIN, double buffered.
// BM=128, BK=16, TM=8 fixed; 256 threads. MODE 0: store to g_gl (gate).
// MODE 1: scale by routed weight and store to g_aext (expert h').
// ---------------------------------------------------------------------------
template<int BN, int TN, int MODE>
__global__ __launch_bounds__(256) void sgemm128(const float* __restrict__ A,
                                                const float* __restrict__ B) {
    constexpr int BM = 128, BK = 16, TM = 8;
    constexpr int LA = BM + 4, LB = BN + 4;
    constexpr int BP = BN / 64;
    __shared__ float As[2][BK][LA];
    __shared__ float Bs[2][BK][LB];
    const int tid = threadIdx.x;
    const int tx = tid % (BN / TN);
    const int ty = tid / (BN / TN);
    const int arow = tid >> 2;
    const int acol = (tid & 3) * 4;

    const float* Ag = A + (blockIdx.y * BM + arow) * DIN + acol;
    const float* Bg = B + (blockIdx.x * BN + arow) * DIN + acol;

    float acc[TM][TN];
    #pragma unroll
    for (int i = 0; i < TM; i++)
        #pragma unroll
        for (int j = 0; j < TN; j++) acc[i][j] = 0.f;

    float4 av[2], bv[BP];

    auto sts = [&](int buf) {
        #pragma unroll
        for (int p = 0; p < 2; p++) {
            As[buf][acol + 0][arow + p * 64] = av[p].x;
            As[buf][acol + 1][arow + p * 64] = av[p].y;
            As[buf][acol + 2][arow + p * 64] = av[p].z;
            As[buf][acol + 3][arow + p * 64] = av[p].w;
        }
        #pragma unroll
        for (int p = 0; p < BP; p++) {
            Bs[buf][acol + 0][arow + p * 64] = bv[p].x;
            Bs[buf][acol + 1][arow + p * 64] = bv[p].y;
            Bs[buf][acol + 2][arow + p * 64] = bv[p].z;
            Bs[buf][acol + 3][arow + p * 64] = bv[p].w;
        }
    };

    #pragma unroll
    for (int p = 0; p < 2; p++)  av[p] = *(const float4*)(Ag + p * 64 * DIN);
    #pragma unroll
    for (int p = 0; p < BP; p++) bv[p] = *(const float4*)(Bg + p * 64 * DIN);
    sts(0);
    __syncthreads();

    const int nk = DIN / BK;
    for (int kt = 0; kt < nk; kt++) {
        const int cur = kt & 1;
        if (kt + 1 < nk) {
            #pragma unroll
            for (int p = 0; p < 2; p++)
                av[p] = *(const float4*)(Ag + (kt + 1) * BK + p * 64 * DIN);
            #pragma unroll
            for (int p = 0; p < BP; p++)
                bv[p] = *(const float4*)(Bg + (kt + 1) * BK + p * 64 * DIN);
        }
        #pragma unroll
        for (int kk = 0; kk < BK; kk++) {
            float a[TM], b[TN];
            #pragma unroll
            for (int i = 0; i < TM; i++) a[i] = As[cur][kk][ty * TM + i];
            #pragma unroll
            for (int j = 0; j < TN; j++) b[j] = Bs[cur][kk][tx * TN + j];
            #pragma unroll
            for (int i = 0; i < TM; i++)
                #pragma unroll
                for (int j = 0; j < TN; j++) acc[i][j] += a[i] * b[j];
        }
        if (kt + 1 < nk) {
            sts(cur ^ 1);
            __syncthreads();
        }
    }

    const int row0 = blockIdx.y * BM + ty * TM;
    const int col0 = blockIdx.x * BN + tx * TN;
    if (MODE == 0) {
        #pragma unroll
        for (int i = 0; i < TM; i++)
            #pragma unroll
            for (int j = 0; j < TN; j++)
                g_gl[(row0 + i) * NRTR + col0 + j] = acc[i][j];
    } else {
        const int e = col0 >> 5;  // TN=8 tile never crosses a 32-col expert block
        #pragma unroll
        for (int i = 0; i < TM; i++) {
            float wv = g_w[(row0 + i) * NE + e];
            #pragma unroll
            for (int j = 0; j < TN; j++)
                g_aext[(row0 + i) * KEXT + col0 + j] = acc[i][j] * wv;
        }
    }
}

// ---------------------------------------------------------------------------
// Main fused GEMM: out = x @ shared_w^T (K=4096, seg 0)
//                      + [h'|w|0] @ [u_flat|bias|0]^T (K=272, seg 1)
//                      + shared_b
// ---------------------------------------------------------------------------
__global__ __launch_bounds__(256) void main_gemm(const float* __restrict__ X,
                                                 const float* __restrict__ W,
                                                 const float* __restrict__ Bias,
                                                 float* __restrict__ C) {
    constexpr int BK = 16;
    constexpr int LA = 132, LB = 132;
    __shared__ float As[2][BK][LA];
    __shared__ float Bs[2][BK][LB];
    const int tid = threadIdx.x;
    const int tx = tid & 15, ty = tid >> 4;
    const int arow = tid >> 2;
    const int acol = (tid & 3) * 4;

    float acc[8][8];
    #pragma unroll
    for (int i = 0; i < 8; i++)
        #pragma unroll
        for (int j = 0; j < 8; j++) acc[i][j] = 0.f;

    float4 av[2], bv[2];
    auto sts = [&](int buf) {
        #pragma unroll
        for (int p = 0; p < 2; p++) {
            As[buf][acol + 0][arow + p * 64] = av[p].x;
            As[buf][acol + 1][arow + p * 64] = av[p].y;
            As[buf][acol + 2][arow + p * 64] = av[p].z;
            As[buf][acol + 3][arow + p * 64] = av[p].w;
            Bs[buf][acol + 0][arow + p * 64] = bv[p].x;
            Bs[buf][acol + 1][arow + p * 64] = bv[p].y;
            Bs[buf][acol + 2][arow + p * 64] = bv[p].z;
            Bs[buf][acol + 3][arow + p * 64] = bv[p].w;
        }
    };

    #pragma unroll 1
    for (int s = 0; s < 2; s++) {
        const float* Ag;
        const float* Bg;
        int ld, nk;
        if (s == 0) {
            Ag = X + (blockIdx.y * 128 + arow) * DIN + acol;
            Bg = W + (blockIdx.x * 128 + arow) * DIN + acol;
            ld = DIN; nk = DIN / BK;
        } else {
            Ag = g_aext + (blockIdx.y * 128 + arow) * KEXT + acol;
            Bg = g_bext + (blockIdx.x * 128 + arow) * KEXT + acol;
            ld = KEXT; nk = KEXT / BK;
        }
        av[0] = *(const float4*)(Ag);
        av[1] = *(const float4*)(Ag + 64 * ld);
        bv[0] = *(const float4*)(Bg);
        bv[1] = *(const float4*)(Bg + 64 * ld);
        __syncthreads();   // previous segment's last compute must finish before reuse
        sts(0);
        __syncthreads();

        for (int kt = 0; kt < nk; kt++) {
            const int cur = kt & 1;
            if (kt + 1 < nk) {
                av[0] = *(const float4*)(Ag + (kt + 1) * BK);
                av[1] = *(const float4*)(Ag + (kt + 1) * BK + 64 * ld);
                bv[0] = *(const float4*)(Bg + (kt + 1) * BK);
                bv[1] = *(const float4*)(Bg + (kt + 1) * BK + 64 * ld);
            }
            #pragma unroll
            for (int kk = 0; kk < BK; kk++) {
                float a[8], b[8];
                #pragma unroll
                for (int i = 0; i < 8; i++) a[i] = As[cur][kk][ty * 8 + i];
                #pragma unroll
                for (int j = 0; j < 8; j++) b[j] = Bs[cur][kk][tx * 8 + j];
                #pragma unroll
                for (int i = 0; i < 8; i++)
                    #pragma unroll
                    for (int j = 0; j < 8; j++) acc[i][j] += a[i] * b[j];
            }
            if (kt + 1 < nk) {
                sts(cur ^ 1);
                __syncthreads();
            }
        }
    }

    const int row0 = blockIdx.y * 128 + ty * 8;
    const int col0 = blockIdx.x * 128 + tx * 8;
    #pragma unroll
    for (int i = 0; i < 8; i++)
        #pragma unroll
        for (int j = 0; j < 8; j++)
            C[(row0 + i) * DOUT + col0 + j] = acc[i][j] + Bias[col0 + j];
}

// ---------------------------------------------------------------------------
extern "C" void kernel_launch(void* const* d_in, const int* in_sizes, int n_in,
                              void* d_out, int out_size) {
    const float* x    = (const float*)d_in[0];  // [T, 4096]
    const float* gate = (const float*)d_in[1];  // [64, 4096]
    const float* shw  = (const float*)d_in[2];  // [4096, 4096]
    const float* shb  = (const float*)d_in[3];  // [4096]
    const float* u    = (const float*)d_in[4];  // [8, 4096, 32]
    const float* svh  = (const float*)d_in[5];  // [8, 32, 4096] -> [256, 4096]
    const float* eb   = (const float*)d_in[6];  // [8, 4096]
    float* out = (float*)d_out;                 // [T, 4096]

    bext_kernel<<<(DOUT * KEXT + 255) / 256, 256>>>(u, eb);
    sgemm128<64, 4, 0><<<dim3(1, TT / 128), 256>>>(x, gate);            // gate logits
    routing_kernel<<<(TT + 255) / 256, 256>>>();                        // top2 weights
    sgemm128<128, 8, 1><<<dim3(256 / 128, TT / 128), 256>>>(x, svh);    // h' (scaled)
    main_gemm<<<dim3(DOUT / 128, TT / 128), 256>>>(x, shw, shb, out);   // fused output
}